// round 12
// baseline (speedup 1.0000x reference)
#include <cuda_runtime.h>

// GAE backward scan as a parallel suffix scan of affine maps.
// gae_t = delta_t + c_t * gae_{t+1},  c_t = GAMMA*LMBDA*nd_t  (nd in {0,1})
//
// R12: R10 champion config (512 thr, VPT=4, .cg loads/.cs stores, 48
// warps/SM) but TWO adjacent rows per CTA (grid 2048): 8 front-batched
// LDG.128 per thread (2x MLP) and one shared barrier pair for both rows'
// cross-warp combines (threads 0-15 row0, 16-31 row1). regs capped at 42
// via __launch_bounds__(512,3) to hold 3 CTAs/SM.

#define GAMMA 0.99f
#define LMBDA 0.95f
#define KCOEF (GAMMA * LMBDA)   // 0.9405f

constexpr int T_LEN   = 2048;
constexpr int THREADS = 512;
constexpr int VPT     = T_LEN / THREADS;  // 4 elements per thread
constexpr int NWARP   = THREADS / 32;     // 16
constexpr size_t SMEM_BYTES = 64 * 1024;  // pins residency at 3 blocks/SM

__global__ __launch_bounds__(THREADS, 3)
void gae_kernel(const float* __restrict__ reward,
                const int*   __restrict__ terminated,
                const float* __restrict__ value,
                const float* __restrict__ next_value,
                float*       __restrict__ adv_out,
                float*       __restrict__ ret_out)
{
    extern __shared__ float ballast[];               // residency pin only
    __shared__ float sA[2][NWARP], sB[2][NWARP], gIn[2][NWARP];

    const int tid  = threadIdx.x;
    const int lane = tid & 31;
    const int warp = tid >> 5;
    const unsigned FULL = 0xffffffffu;

    const long long base0 =
        (long long)(2 * blockIdx.x) * T_LEN + (long long)tid * VPT;
    const long long base1 = base0 + T_LEN;

    // ---- Front-batch ALL 8 vector loads (2 rows x 4 arrays), L2-only ----
    float4 rr0 = __ldcg(reinterpret_cast<const float4*>(reward     + base0));
    float4 vv0 = __ldcg(reinterpret_cast<const float4*>(value      + base0));
    float4 nn0 = __ldcg(reinterpret_cast<const float4*>(next_value + base0));
    int4   tt0 = __ldcg(reinterpret_cast<const int4*>(terminated   + base0));
    float4 rr1 = __ldcg(reinterpret_cast<const float4*>(reward     + base1));
    float4 vv1 = __ldcg(reinterpret_cast<const float4*>(value      + base1));
    float4 nn1 = __ldcg(reinterpret_cast<const float4*>(next_value + base1));
    int4   tt1 = __ldcg(reinterpret_cast<const int4*>(terminated   + base1));

    // ---- Per-row delta / mask ----
    float d0[VPT], v0[VPT], d1[VPT], v1[VPT];
    unsigned m0 = 0, m1 = 0;

    v0[0]=vv0.x; v0[1]=vv0.y; v0[2]=vv0.z; v0[3]=vv0.w;
    d0[0] = (tt0.x==0) ? fmaf(GAMMA, nn0.x, rr0.x-vv0.x) : (rr0.x-vv0.x);
    d0[1] = (tt0.y==0) ? fmaf(GAMMA, nn0.y, rr0.y-vv0.y) : (rr0.y-vv0.y);
    d0[2] = (tt0.z==0) ? fmaf(GAMMA, nn0.z, rr0.z-vv0.z) : (rr0.z-vv0.z);
    d0[3] = (tt0.w==0) ? fmaf(GAMMA, nn0.w, rr0.w-vv0.w) : (rr0.w-vv0.w);
    m0 |= (tt0.x==0?1u:0u)<<0;  m0 |= (tt0.y==0?1u:0u)<<1;
    m0 |= (tt0.z==0?1u:0u)<<2;  m0 |= (tt0.w==0?1u:0u)<<3;

    v1[0]=vv1.x; v1[1]=vv1.y; v1[2]=vv1.z; v1[3]=vv1.w;
    d1[0] = (tt1.x==0) ? fmaf(GAMMA, nn1.x, rr1.x-vv1.x) : (rr1.x-vv1.x);
    d1[1] = (tt1.y==0) ? fmaf(GAMMA, nn1.y, rr1.y-vv1.y) : (rr1.y-vv1.y);
    d1[2] = (tt1.z==0) ? fmaf(GAMMA, nn1.z, rr1.z-vv1.z) : (rr1.z-vv1.z);
    d1[3] = (tt1.w==0) ? fmaf(GAMMA, nn1.w, rr1.w-vv1.w) : (rr1.w-vv1.w);
    m1 |= (tt1.x==0?1u:0u)<<0;  m1 |= (tt1.y==0?1u:0u)<<1;
    m1 |= (tt1.z==0?1u:0u)<<2;  m1 |= (tt1.w==0?1u:0u)<<3;

    // ---- Fold + warp suffix-scan, both rows, then ONE barrier pair ----
    float Ae0, Be0, Ae1, Be1;
    {
        // row 0
        float A = 1.0f, B = 0.0f;
        #pragma unroll
        for (int j = 0; j < VPT; ++j) {
            B = fmaf(A, d0[j], B);
            A = ((m0 >> j) & 1u) ? A * KCOEF : 0.0f;
        }
        float Ai = A, Bi = B;
        #pragma unroll
        for (int off = 1; off < 32; off <<= 1) {
            float Ao = __shfl_down_sync(FULL, Ai, off);
            float Bo = __shfl_down_sync(FULL, Bi, off);
            if (lane + off < 32) { Bi = fmaf(Ai, Bo, Bi); Ai = Ai * Ao; }
        }
        Ae0 = __shfl_down_sync(FULL, Ai, 1);
        Be0 = __shfl_down_sync(FULL, Bi, 1);
        if (lane == 31) { Ae0 = 1.0f; Be0 = 0.0f; }
        if (lane == 0) { sA[0][warp] = Ai; sB[0][warp] = Bi; }
    }
    {
        // row 1
        float A = 1.0f, B = 0.0f;
        #pragma unroll
        for (int j = 0; j < VPT; ++j) {
            B = fmaf(A, d1[j], B);
            A = ((m1 >> j) & 1u) ? A * KCOEF : 0.0f;
        }
        float Ai = A, Bi = B;
        #pragma unroll
        for (int off = 1; off < 32; off <<= 1) {
            float Ao = __shfl_down_sync(FULL, Ai, off);
            float Bo = __shfl_down_sync(FULL, Bi, off);
            if (lane + off < 32) { Bi = fmaf(Ai, Bo, Bi); Ai = Ai * Ao; }
        }
        Ae1 = __shfl_down_sync(FULL, Ai, 1);
        Be1 = __shfl_down_sync(FULL, Bi, 1);
        if (lane == 31) { Ae1 = 1.0f; Be1 = 0.0f; }
        if (lane == 0) { sA[1][warp] = Ai; sB[1][warp] = Bi; }
    }
    __syncthreads();
    if (tid < 2 * NWARP) {
        const int r = tid >> 4;       // 0 or 1
        const int t = tid & (NWARP - 1);
        float g = 0.0f;
        #pragma unroll
        for (int w = NWARP - 1; w > 0; --w)
            if (w > t) g = fmaf(sA[r][w], g, sB[r][w]);
        gIn[r][t] = g;
    }
    __syncthreads();

    // ---- Replay + store, row 0 ----
    {
        float g = fmaf(Ae0, gIn[0][warp], Be0);
        float adv[VPT];
        #pragma unroll
        for (int j = VPT - 1; j >= 0; --j) {
            g = ((m0 >> j) & 1u) ? fmaf(KCOEF, g, d0[j]) : d0[j];
            adv[j] = g;
        }
        float4 av, rt;
        av.x = adv[0]; av.y = adv[1]; av.z = adv[2]; av.w = adv[3];
        rt.x = av.x + v0[0]; rt.y = av.y + v0[1];
        rt.z = av.z + v0[2]; rt.w = av.w + v0[3];
        __stcs(reinterpret_cast<float4*>(adv_out + base0), av);
        __stcs(reinterpret_cast<float4*>(ret_out + base0), rt);
    }
    // ---- Replay + store, row 1 ----
    {
        float g = fmaf(Ae1, gIn[1][warp], Be1);
        float adv[VPT];
        #pragma unroll
        for (int j = VPT - 1; j >= 0; --j) {
            g = ((m1 >> j) & 1u) ? fmaf(KCOEF, g, d1[j]) : d1[j];
            adv[j] = g;
        }
        float4 av, rt;
        av.x = adv[0]; av.y = adv[1]; av.z = adv[2]; av.w = adv[3];
        rt.x = av.x + v1[0]; rt.y = av.y + v1[1];
        rt.z = av.z + v1[2]; rt.w = av.w + v1[3];
        __stcs(reinterpret_cast<float4*>(adv_out + base1), av);
        __stcs(reinterpret_cast<float4*>(ret_out + base1), rt);
    }
}

extern "C" void kernel_launch(void* const* d_in, const int* in_sizes, int n_in,
                              void* d_out, int out_size)
{
    const float* reward     = (const float*)d_in[0];
    const int*   terminated = (const int*)  d_in[1];
    const float* value      = (const float*)d_in[2];
    const float* next_value = (const float*)d_in[3];

    const int n = in_sizes[0];          // B * T
    const int B = n / T_LEN;

    float* adv_out = (float*)d_out;          // advantages: first n elements
    float* ret_out = (float*)d_out + n;      // returns:    next n elements

    cudaFuncSetAttribute(gae_kernel,
                         cudaFuncAttributeMaxDynamicSharedMemorySize,
                         (int)SMEM_BYTES);

    gae_kernel<<<B / 2, THREADS, SMEM_BYTES>>>(reward, terminated, value,
                                               next_value, adv_out, ret_out);
}

// round 13
// speedup vs baseline: 1.2071x; 1.2071x over previous
#include <cuda_runtime.h>

// GAE backward scan as a parallel suffix scan of affine maps.
// gae_t = delta_t + c_t * gae_{t+1},  c_t = GAMMA*LMBDA*nd_t  (nd in {0,1})
//
// R13: R10 champion (512 thr, VPT=4, .cg loads/.cs stores, 48 warps/SM via
// 64KB smem pin, grid=4096) with the second __syncthreads removed: each
// thread computes its warp's cross-warp suffix composite directly from
// sA/sB after ONE barrier (15 predicated FMAs, broadcast LDS).
// Design-space summary: occ sweep peaked at 48 w/SM; VPT=4 (full-sector
// LDG.128) required; persistence/cp.async/multi-row all refuted.

#define GAMMA 0.99f
#define LMBDA 0.95f
#define KCOEF (GAMMA * LMBDA)   // 0.9405f

constexpr int T_LEN   = 2048;
constexpr int THREADS = 512;
constexpr int VPT     = T_LEN / THREADS;  // 4 elements per thread
constexpr int NWARP   = THREADS / 32;     // 16
constexpr size_t SMEM_BYTES = 64 * 1024;  // pins residency at 3 blocks/SM

__global__ __launch_bounds__(THREADS)
void gae_kernel(const float* __restrict__ reward,
                const int*   __restrict__ terminated,
                const float* __restrict__ value,
                const float* __restrict__ next_value,
                float*       __restrict__ adv_out,
                float*       __restrict__ ret_out)
{
    extern __shared__ float smem[];
    float* sA = smem;            // [NWARP]
    float* sB = smem + NWARP;    // [NWARP]

    const int tid  = threadIdx.x;
    const int lane = tid & 31;
    const int warp = tid >> 5;

    const long long base = (long long)blockIdx.x * T_LEN + (long long)tid * VPT;

    // ---- L2-only loads (.cg): one float4/int4 per array, full sectors ----
    float4 rr = __ldcg(reinterpret_cast<const float4*>(reward     + base));
    float4 vv = __ldcg(reinterpret_cast<const float4*>(value      + base));
    float4 nn = __ldcg(reinterpret_cast<const float4*>(next_value + base));
    int4   tt = __ldcg(reinterpret_cast<const int4*>(terminated   + base));

    float v[VPT] = {vv.x, vv.y, vv.z, vv.w};
    float delta[VPT];
    unsigned mask = 0;
    // delta = r - v + GAMMA*nv*nd ; nd = !terminated
    delta[0] = (tt.x == 0) ? fmaf(GAMMA, nn.x, rr.x - vv.x) : (rr.x - vv.x);
    delta[1] = (tt.y == 0) ? fmaf(GAMMA, nn.y, rr.y - vv.y) : (rr.y - vv.y);
    delta[2] = (tt.z == 0) ? fmaf(GAMMA, nn.z, rr.z - vv.z) : (rr.z - vv.z);
    delta[3] = (tt.w == 0) ? fmaf(GAMMA, nn.w, rr.w - vv.w) : (rr.w - vv.w);
    mask |= (tt.x == 0 ? 1u : 0u) << 0;
    mask |= (tt.y == 0 ? 1u : 0u) << 1;
    mask |= (tt.z == 0 ? 1u : 0u) << 2;
    mask |= (tt.w == 0 ? 1u : 0u) << 3;

    // ---- Fold chunk into one affine composite (j=0 earliest/outermost) ----
    float A = 1.0f, B = 0.0f;
    #pragma unroll
    for (int j = 0; j < VPT; ++j) {
        B = fmaf(A, delta[j], B);
        A = ((mask >> j) & 1u) ? A * KCOEF : 0.0f;
    }

    // ---- Warp-level inclusive SUFFIX scan (self = earlier = outer) ----
    const unsigned FULL = 0xffffffffu;
    float Ai = A, Bi = B;
    #pragma unroll
    for (int off = 1; off < 32; off <<= 1) {
        float Ao = __shfl_down_sync(FULL, Ai, off);
        float Bo = __shfl_down_sync(FULL, Bi, off);
        if (lane + off < 32) {
            Bi = fmaf(Ai, Bo, Bi);
            Ai = Ai * Ao;
        }
    }
    // Exclusive within warp: composite of lanes (lane+1 .. 31)
    float Ae = __shfl_down_sync(FULL, Ai, 1);
    float Be = __shfl_down_sync(FULL, Bi, 1);
    if (lane == 31) { Ae = 1.0f; Be = 0.0f; }

    // ---- Cross-warp combine: ONE barrier, every thread folds sA/sB ----
    if (lane == 0) { sA[warp] = Ai; sB[warp] = Bi; }
    __syncthreads();
    float gw = 0.0f;   // gae entering this warp from later warps
    #pragma unroll
    for (int w = NWARP - 1; w > 0; --w)
        if (w > warp) gw = fmaf(sA[w], gw, sB[w]);

    // Carry entering this thread's chunk (gae just past chunk end)
    float g = fmaf(Ae, gw, Be);

    // ---- Replay chunk backward, materialize advantages ----
    float adv[VPT];
    #pragma unroll
    for (int j = VPT - 1; j >= 0; --j) {
        g = ((mask >> j) & 1u) ? fmaf(KCOEF, g, delta[j]) : delta[j];
        adv[j] = g;
    }

    // ---- Evict-first stores: advantages, then returns = adv + value ----
    float4 av, rt;
    av.x = adv[0]; av.y = adv[1]; av.z = adv[2]; av.w = adv[3];
    rt.x = av.x + v[0];
    rt.y = av.y + v[1];
    rt.z = av.z + v[2];
    rt.w = av.w + v[3];
    __stcs(reinterpret_cast<float4*>(adv_out + base), av);
    __stcs(reinterpret_cast<float4*>(ret_out + base), rt);
}

extern "C" void kernel_launch(void* const* d_in, const int* in_sizes, int n_in,
                              void* d_out, int out_size)
{
    const float* reward     = (const float*)d_in[0];
    const int*   terminated = (const int*)  d_in[1];
    const float* value      = (const float*)d_in[2];
    const float* next_value = (const float*)d_in[3];

    const int n = in_sizes[0];          // B * T
    const int B = n / T_LEN;

    float* adv_out = (float*)d_out;          // advantages: first n elements
    float* ret_out = (float*)d_out + n;      // returns:    next n elements

    cudaFuncSetAttribute(gae_kernel,
                         cudaFuncAttributeMaxDynamicSharedMemorySize,
                         (int)SMEM_BYTES);

    gae_kernel<<<B, THREADS, SMEM_BYTES>>>(reward, terminated, value,
                                           next_value, adv_out, ret_out);
}

// round 14
// speedup vs baseline: 1.2454x; 1.0318x over previous
#include <cuda_runtime.h>

// GAE backward scan as a parallel suffix scan of affine maps.
// gae_t = delta_t + c_t * gae_{t+1},  c_t = GAMMA*LMBDA*nd_t  (nd in {0,1})
//
// FINAL (== R10 champion, kernel 27.87us, DRAM 74.6%):
//   - one CTA per row, 512 threads, VPT=4: one float4/int4 per array per
//     thread -> every LDG.128 covers full 128B sectors (coalescing optimum)
//   - 48 warps/SM via 64KB dynamic-smem residency pin (occupancy sweep
//     unimodal: 32w=56.7%, 48w=74.6%, 64w=64.0% DRAM)
//   - __ldcg loads (L2-only; L1 has zero reuse) + __stcs stores
//     (write stream never re-read) — best of the measured policy matrix
//   - two-barrier cross-warp combine (16-thread fold; cheaper than
//     all-thread LDS fold per R13 measurement)
// Refuted alternatives: persistent CTAs (R7/R11), cp.async pipeline (R11),
// 2 rows/CTA (R12), barrier elimination (R13), VPT=8 (R2/R3).

#define GAMMA 0.99f
#define LMBDA 0.95f
#define KCOEF (GAMMA * LMBDA)   // 0.9405f

constexpr int T_LEN   = 2048;
constexpr int THREADS = 512;
constexpr int VPT     = T_LEN / THREADS;  // 4 elements per thread
constexpr int NWARP   = THREADS / 32;     // 16
constexpr size_t SMEM_BYTES = 64 * 1024;  // pins residency at 3 blocks/SM

__global__ __launch_bounds__(THREADS)
void gae_kernel(const float* __restrict__ reward,
                const int*   __restrict__ terminated,
                const float* __restrict__ value,
                const float* __restrict__ next_value,
                float*       __restrict__ adv_out,
                float*       __restrict__ ret_out)
{
    extern __shared__ float smem[];
    float* sA  = smem;            // [NWARP]
    float* sB  = smem + NWARP;    // [NWARP]
    float* gIn = smem + 2*NWARP;  // [NWARP]

    const int tid  = threadIdx.x;
    const int lane = tid & 31;
    const int warp = tid >> 5;

    const long long base = (long long)blockIdx.x * T_LEN + (long long)tid * VPT;

    // ---- L2-only loads (.cg): one float4/int4 per array, full sectors ----
    float4 rr = __ldcg(reinterpret_cast<const float4*>(reward     + base));
    float4 vv = __ldcg(reinterpret_cast<const float4*>(value      + base));
    float4 nn = __ldcg(reinterpret_cast<const float4*>(next_value + base));
    int4   tt = __ldcg(reinterpret_cast<const int4*>(terminated   + base));

    float v[VPT] = {vv.x, vv.y, vv.z, vv.w};
    float delta[VPT];
    unsigned mask = 0;
    // delta = r - v + GAMMA*nv*nd ; nd = !terminated
    delta[0] = (tt.x == 0) ? fmaf(GAMMA, nn.x, rr.x - vv.x) : (rr.x - vv.x);
    delta[1] = (tt.y == 0) ? fmaf(GAMMA, nn.y, rr.y - vv.y) : (rr.y - vv.y);
    delta[2] = (tt.z == 0) ? fmaf(GAMMA, nn.z, rr.z - vv.z) : (rr.z - vv.z);
    delta[3] = (tt.w == 0) ? fmaf(GAMMA, nn.w, rr.w - vv.w) : (rr.w - vv.w);
    mask |= (tt.x == 0 ? 1u : 0u) << 0;
    mask |= (tt.y == 0 ? 1u : 0u) << 1;
    mask |= (tt.z == 0 ? 1u : 0u) << 2;
    mask |= (tt.w == 0 ? 1u : 0u) << 3;

    // ---- Fold chunk into one affine composite (j=0 earliest/outermost) ----
    float A = 1.0f, B = 0.0f;
    #pragma unroll
    for (int j = 0; j < VPT; ++j) {
        B = fmaf(A, delta[j], B);
        A = ((mask >> j) & 1u) ? A * KCOEF : 0.0f;
    }

    // ---- Warp-level inclusive SUFFIX scan (self = earlier = outer) ----
    const unsigned FULL = 0xffffffffu;
    float Ai = A, Bi = B;
    #pragma unroll
    for (int off = 1; off < 32; off <<= 1) {
        float Ao = __shfl_down_sync(FULL, Ai, off);
        float Bo = __shfl_down_sync(FULL, Bi, off);
        if (lane + off < 32) {
            Bi = fmaf(Ai, Bo, Bi);
            Ai = Ai * Ao;
        }
    }
    // Exclusive within warp: composite of lanes (lane+1 .. 31)
    float Ae = __shfl_down_sync(FULL, Ai, 1);
    float Be = __shfl_down_sync(FULL, Bi, 1);
    if (lane == 31) { Ae = 1.0f; Be = 0.0f; }

    // ---- Cross-warp combine (16 warps, two barriers) ----
    if (lane == 0) { sA[warp] = Ai; sB[warp] = Bi; }
    __syncthreads();
    if (tid < NWARP) {
        float g = 0.0f;
        #pragma unroll
        for (int w = NWARP - 1; w > 0; --w)
            if (w > tid) g = fmaf(sA[w], g, sB[w]);
        gIn[tid] = g;
    }
    __syncthreads();

    // Carry entering this thread's chunk (gae just past chunk end)
    float g = fmaf(Ae, gIn[warp], Be);

    // ---- Replay chunk backward, materialize advantages ----
    float adv[VPT];
    #pragma unroll
    for (int j = VPT - 1; j >= 0; --j) {
        g = ((mask >> j) & 1u) ? fmaf(KCOEF, g, delta[j]) : delta[j];
        adv[j] = g;
    }

    // ---- Evict-first stores: advantages, then returns = adv + value ----
    float4 av, rt;
    av.x = adv[0]; av.y = adv[1]; av.z = adv[2]; av.w = adv[3];
    rt.x = av.x + v[0];
    rt.y = av.y + v[1];
    rt.z = av.z + v[2];
    rt.w = av.w + v[3];
    __stcs(reinterpret_cast<float4*>(adv_out + base), av);
    __stcs(reinterpret_cast<float4*>(ret_out + base), rt);
}

extern "C" void kernel_launch(void* const* d_in, const int* in_sizes, int n_in,
                              void* d_out, int out_size)
{
    const float* reward     = (const float*)d_in[0];
    const int*   terminated = (const int*)  d_in[1];
    const float* value      = (const float*)d_in[2];
    const float* next_value = (const float*)d_in[3];

    const int n = in_sizes[0];          // B * T
    const int B = n / T_LEN;

    float* adv_out = (float*)d_out;          // advantages: first n elements
    float* ret_out = (float*)d_out + n;      // returns:    next n elements

    cudaFuncSetAttribute(gae_kernel,
                         cudaFuncAttributeMaxDynamicSharedMemorySize,
                         (int)SMEM_BYTES);

    gae_kernel<<<B, THREADS, SMEM_BYTES>>>(reward, terminated, value,
                                           next_value, adv_out, ret_out);
}